// round 12
// baseline (speedup 1.0000x reference)
#include <cuda_runtime.h>
#include <mma.h>
#include <cstdint>

using namespace nvcuda;

#define NN 8192
#define DD 256
#define NE 131072

#define BM 64
#define BN 256
#define BK 32
#define LDAS 36
#define LDBS 260
#define LDCS 260
#define STAGE_FLOATS (BM * LDAS + BK * LDBS)   // 10624
#define NSTAGE 3
#define SMEM_BYTES (NSTAGE * STAGE_FLOATS * 4) // 127488

// scratch (device globals; no allocations allowed)
__device__ float g_buf0[NN * DD];
__device__ float g_buf1[NN * DD];
__device__ float g_h[NN * DD];
__device__ float g_gout[NN * DD];
__device__ float g_bt[NN * DD];        // tf32-RN pre-rounded B operand (level 0)
__device__ float g_bt2[NN * DD];       // pre-rounded output of level 0 (level-1 B)
__device__ float g_wt1[DD * DD];       // pre-rounded W_same
__device__ float g_wt2[DD * DD];       // pre-rounded W_top
__device__ int   g_cnt[NN];
__device__ int   g_rowstart[NN + 1];
__device__ int   g_cursor[NN];
__device__ int   g_csr_src[NE];
__device__ float g_dinv[NN];

__device__ __forceinline__ void cp_async16(void* smem_ptr, const void* gmem_ptr)
{
    uint32_t s = (uint32_t)__cvta_generic_to_shared(smem_ptr);
    asm volatile("cp.async.cg.shared.global [%0], [%1], 16;\n" :: "r"(s), "l"(gmem_ptr));
}
#define CP_COMMIT() asm volatile("cp.async.commit_group;\n" ::)

__device__ __forceinline__ float tf32_rna(float x)
{
    uint32_t u;
    asm("cvt.rna.tf32.f32 %0, %1;" : "=r"(u) : "f"(x));
    return __uint_as_float(u);
}

// ---------------------------------------------------------------------------
// Pre-round fp32 -> tf32(RN) bit pattern (low 13 bits zero). nElem4 float4s.
// ---------------------------------------------------------------------------
__global__ void round_tf32_kernel(const float* __restrict__ src, float* __restrict__ dst,
                                  int nElem4)
{
    int i = blockIdx.x * blockDim.x + threadIdx.x;
    if (i >= nElem4) return;
    float4 v = ((const float4*)src)[i];
    float4 o;
    o.x = tf32_rna(v.x);
    o.y = tf32_rna(v.y);
    o.z = tf32_rna(v.z);
    o.w = tf32_rna(v.w);
    ((float4*)dst)[i] = o;
}

// ---------------------------------------------------------------------------
// GEMM: C = A[M,K] @ B[K,256]; FUSE: Y = (resid + C) * 1/(rowsum(A)+1)
// 512 threads = 16 warps, warp tile 16x64. 3-stage cp.async pipeline.
// A tile is tf32-RN converted IN PLACE in smem once per tile (rowsum fused);
// B must be pre-rounded to tf32 bits. Mainloop is pure LDS-frag + HMMA.
// If Yt != nullptr (FUSE only), also writes tf32-rounded copy of Y.
// ---------------------------------------------------------------------------
template <bool FUSE>
__global__ __launch_bounds__(512) void gemm_kernel(
    const float* __restrict__ A, int lda,
    const float* __restrict__ B, int ldb,
    int K,
    const float* __restrict__ resid,
    float* __restrict__ Y,
    float* __restrict__ Yt)
{
    extern __shared__ float pool[];
    __shared__ float invs[BM];

    const int tid = threadIdx.x;
    const int wid = tid >> 5;
    const int wm = wid >> 2;            // 0..3 : 16-row band
    const int wn = wid & 3;             // 0..3 : 64-col band
    const int m0 = blockIdx.y * BM;

    wmma::fragment<wmma::accumulator, 16, 16, 8, float> cf[4];
#pragma unroll
    for (int j = 0; j < 4; j++) wmma::fill_fragment(cf[j], 0.0f);

    float rs = 0.0f;
    const int nIter = K / BK;
    const int ar = tid >> 3;            // cvt-pass row 0..63
    const int ac4 = (tid & 7) * 4;      // cvt-pass col 0..28

    // ---- prologue: stages 0 and 1
#pragma unroll
    for (int st = 0; st < 2; st++) {
        float* As = pool + st * STAGE_FLOATS;
        float* Bs = As + BM * LDAS;
        const int k0 = st * BK;
        cp_async16(&As[ar * LDAS + ac4], &A[(size_t)(m0 + ar) * lda + k0 + ac4]);
#pragma unroll
        for (int i = 0; i < 4; i++) {
            int e = tid + i * 512;
            int r = e >> 6, c4 = (e & 63) * 4;
            cp_async16(&Bs[r * LDBS + c4], &B[(size_t)(k0 + r) * ldb + c4]);
        }
        CP_COMMIT();
    }

    for (int it = 0; it < nIter; ++it) {
        if (it == nIter - 1) asm volatile("cp.async.wait_group 0;\n" ::);
        else                 asm volatile("cp.async.wait_group 1;\n" ::);
        __syncthreads();

        // issue loads for stage it+2 (buffer reuse safe after barrier)
        const int tn = it + 2;
        if (tn < nIter) {
            float* Asn = pool + (tn % NSTAGE) * STAGE_FLOATS;
            float* Bsn = Asn + BM * LDAS;
            const int k0 = tn * BK;
            cp_async16(&Asn[ar * LDAS + ac4], &A[(size_t)(m0 + ar) * lda + k0 + ac4]);
#pragma unroll
            for (int i = 0; i < 4; i++) {
                int e = tid + i * 512;
                int r = e >> 6, c4 = (e & 63) * 4;
                cp_async16(&Bsn[r * LDBS + c4], &B[(size_t)(k0 + r) * ldb + c4]);
            }
            CP_COMMIT();
        }

        float* As = pool + (it % NSTAGE) * STAGE_FLOATS;
        float* Bs = As + BM * LDAS;

        // ---- in-place tf32-RN conversion of A tile (+ fused rowsum)
        {
            float4 v = *(const float4*)&As[ar * LDAS + ac4];
            if (FUSE) rs += v.x + v.y + v.z + v.w;
            v.x = tf32_rna(v.x);
            v.y = tf32_rna(v.y);
            v.z = tf32_rna(v.z);
            v.w = tf32_rna(v.w);
            *(float4*)&As[ar * LDAS + ac4] = v;
        }
        __syncthreads();

        // ---- pure LDS + HMMA mainloop (no cvt)
#pragma unroll
        for (int kk = 0; kk < BK; kk += 8) {
            wmma::fragment<wmma::matrix_a, 16, 16, 8, wmma::precision::tf32, wmma::row_major> af;
            wmma::fragment<wmma::matrix_b, 16, 16, 8, wmma::precision::tf32, wmma::row_major> bf[4];
            wmma::load_matrix_sync(af, &As[(wm * 16) * LDAS + kk], LDAS);
#pragma unroll
            for (int j = 0; j < 4; j++)
                wmma::load_matrix_sync(bf[j], &Bs[kk * LDBS + wn * 64 + j * 16], LDBS);
#pragma unroll
            for (int j = 0; j < 4; j++)
                wmma::mma_sync(cf[j], af, bf[j], cf[j]);
        }
        __syncthreads();
    }

    if (FUSE) {
        float v = rs;
        v += __shfl_down_sync(0xffffffffu, v, 4, 8);
        v += __shfl_down_sync(0xffffffffu, v, 2, 8);
        v += __shfl_down_sync(0xffffffffu, v, 1, 8);
        if ((tid & 7) == 0) invs[tid >> 3] = 1.0f / (v + 1.0f);
        __syncthreads();
    }

    float* Cs = pool;
#pragma unroll
    for (int j = 0; j < 4; j++)
        wmma::store_matrix_sync(&Cs[(wm * 16) * LDCS + wn * 64 + j * 16],
                                cf[j], LDCS, wmma::mem_row_major);
    __syncthreads();
#pragma unroll
    for (int i = 0; i < 8; i++) {
        int e = tid + i * 512;               // 0..4095
        int r = e >> 6, c4 = (e & 63) * 4;
        float4 c = *(float4*)&Cs[r * LDCS + c4];
        if (FUSE) {
            float4 x = *(const float4*)&resid[(size_t)(m0 + r) * DD + c4];
            float s = invs[r];
            c.x = (c.x + x.x) * s;
            c.y = (c.y + x.y) * s;
            c.z = (c.z + x.z) * s;
            c.w = (c.w + x.w) * s;
        }
        *(float4*)&Y[(size_t)(m0 + r) * DD + c4] = c;
        if (FUSE && Yt) {
            float4 t;
            t.x = tf32_rna(c.x);
            t.y = tf32_rna(c.y);
            t.z = tf32_rna(c.z);
            t.w = tf32_rna(c.w);
            *(float4*)&Yt[(size_t)(m0 + r) * DD + c4] = t;
        }
    }
}

// ---------------------------------------------------------------------------
// CSR build + gather GCN
// ---------------------------------------------------------------------------
__global__ void zero_cnt_kernel()
{
    int i = blockIdx.x * blockDim.x + threadIdx.x;
    if (i < NN) g_cnt[i] = 0;
}

__global__ void hist_kernel(const int* __restrict__ dst)
{
    int e = blockIdx.x * blockDim.x + threadIdx.x;
    if (e < NE) atomicAdd(&g_cnt[dst[e]], 1);
}

__global__ __launch_bounds__(1024) void scan_kernel()
{
    __shared__ int sh[1024];
    int t = threadIdx.x;
    int base = t * 8;
    int v[8];
    int s = 0;
#pragma unroll
    for (int i = 0; i < 8; i++) { v[i] = g_cnt[base + i]; s += v[i]; }
    sh[t] = s;
    __syncthreads();
    for (int off = 1; off < 1024; off <<= 1) {
        int x = (t >= off) ? sh[t - off] : 0;
        __syncthreads();
        sh[t] += x;
        __syncthreads();
    }
    int ex = sh[t] - s;
#pragma unroll
    for (int i = 0; i < 8; i++) {
        g_rowstart[base + i] = ex;
        g_cursor[base + i] = ex;
        g_dinv[base + i] = rsqrtf((float)v[i] + 1.0f);
        ex += v[i];
    }
    if (t == 1023) g_rowstart[NN] = ex;
}

__global__ void fill_kernel(const int* __restrict__ src, const int* __restrict__ dst)
{
    int e = blockIdx.x * blockDim.x + threadIdx.x;
    if (e >= NE) return;
    int p = atomicAdd(&g_cursor[dst[e]], 1);
    g_csr_src[p] = src[e];
}

__global__ __launch_bounds__(256) void gather_kernel(
    const float* __restrict__ h, const float* __restrict__ b, float* __restrict__ out)
{
    int wid = threadIdx.x >> 5;
    int lid = threadIdx.x & 31;
    int n = blockIdx.x * 8 + wid;
    if (n >= NN) return;
    int c0 = lid * 8;

    float dn = g_dinv[n];
    float4 b0 = *(const float4*)&b[c0];
    float4 b1 = *(const float4*)&b[c0 + 4];
    float4 h0 = *(const float4*)&h[(size_t)n * DD + c0];
    float4 h1 = *(const float4*)&h[(size_t)n * DD + c0 + 4];
    float sl = dn * dn;
    float4 a0, a1;
    a0.x = b0.x + sl * h0.x; a0.y = b0.y + sl * h0.y;
    a0.z = b0.z + sl * h0.z; a0.w = b0.w + sl * h0.w;
    a1.x = b1.x + sl * h1.x; a1.y = b1.y + sl * h1.y;
    a1.z = b1.z + sl * h1.z; a1.w = b1.w + sl * h1.w;

    int js = g_rowstart[n];
    int je = g_rowstart[n + 1];
    int j = js;
    for (; j + 1 < je; j += 2) {
        int s0 = g_csr_src[j];
        int s1 = g_csr_src[j + 1];
        float w0 = g_dinv[s0] * dn;
        float w1 = g_dinv[s1] * dn;
        float4 p0 = *(const float4*)&h[(size_t)s0 * DD + c0];
        float4 p1 = *(const float4*)&h[(size_t)s0 * DD + c0 + 4];
        float4 q0 = *(const float4*)&h[(size_t)s1 * DD + c0];
        float4 q1 = *(const float4*)&h[(size_t)s1 * DD + c0 + 4];
        a0.x += w0 * p0.x + w1 * q0.x; a0.y += w0 * p0.y + w1 * q0.y;
        a0.z += w0 * p0.z + w1 * q0.z; a0.w += w0 * p0.w + w1 * q0.w;
        a1.x += w0 * p1.x + w1 * q1.x; a1.y += w0 * p1.y + w1 * q1.y;
        a1.z += w0 * p1.z + w1 * q1.z; a1.w += w0 * p1.w + w1 * q1.w;
    }
    if (j < je) {
        int s0 = g_csr_src[j];
        float w0 = g_dinv[s0] * dn;
        float4 p0 = *(const float4*)&h[(size_t)s0 * DD + c0];
        float4 p1 = *(const float4*)&h[(size_t)s0 * DD + c0 + 4];
        a0.x += w0 * p0.x; a0.y += w0 * p0.y; a0.z += w0 * p0.z; a0.w += w0 * p0.w;
        a1.x += w0 * p1.x; a1.y += w0 * p1.y; a1.z += w0 * p1.z; a1.w += w0 * p1.w;
    }
    *(float4*)&out[(size_t)n * DD + c0] = a0;
    *(float4*)&out[(size_t)n * DD + c0 + 4] = a1;
}

extern "C" void kernel_launch(void* const* d_in, const int* in_sizes, int n_in,
                              void* d_out, int out_size)
{
    const float* emb    = (const float*)d_in[0];
    const float* paths  = (const float*)d_in[1];
    const int*   sm_ei  = (const int*)d_in[2];
    const int*   up_ei  = (const int*)d_in[3];
    const float* W_same = (const float*)d_in[4];
    const float* b_same = (const float*)d_in[5];
    const float* W_top  = (const float*)d_in[6];
    const float* b_top  = (const float*)d_in[7];
    float* out = (float*)d_out;

    float *buf0, *buf1, *h, *gout, *bt, *bt2, *wt1, *wt2;
    cudaGetSymbolAddress((void**)&buf0, g_buf0);
    cudaGetSymbolAddress((void**)&buf1, g_buf1);
    cudaGetSymbolAddress((void**)&h, g_h);
    cudaGetSymbolAddress((void**)&gout, g_gout);
    cudaGetSymbolAddress((void**)&bt, g_bt);
    cudaGetSymbolAddress((void**)&bt2, g_bt2);
    cudaGetSymbolAddress((void**)&wt1, g_wt1);
    cudaGetSymbolAddress((void**)&wt2, g_wt2);

    cudaFuncSetAttribute(gemm_kernel<true>,
                         cudaFuncAttributeMaxDynamicSharedMemorySize, SMEM_BYTES);
    cudaFuncSetAttribute(gemm_kernel<false>,
                         cudaFuncAttributeMaxDynamicSharedMemorySize, SMEM_BYTES);

    dim3 ggrid(1, NN / BM);   // (1, 128)
    int nr4 = NN * (DD / 4);
    int nw4 = DD * DD / 4;

    // Launch order keeps the level-0 big GEMM at index 3 (ncu profiles it).
    round_tf32_kernel<<<(nr4 + 255) / 256, 256>>>(emb, bt, nr4);         // 0
    round_tf32_kernel<<<(nw4 + 255) / 256, 256>>>(W_same, wt1, nw4);     // 1
    round_tf32_kernel<<<(nw4 + 255) / 256, 256>>>(W_top, wt2, nw4);      // 2
    gemm_kernel<true><<<ggrid, 512, SMEM_BYTES>>>(                        // 3 <- profiled
        paths, NN, bt, DD, NN, emb, buf0, bt2);
    zero_cnt_kernel<<<NN / 256, 256>>>();                                 // 4
    hist_kernel<<<NE / 256, 256>>>(sm_ei + NE);                           // 5
    scan_kernel<<<1, 1024>>>();                                           // 6
    fill_kernel<<<NE / 256, 256>>>(sm_ei, sm_ei + NE);                    // 7
    gemm_kernel<true><<<ggrid, 512, SMEM_BYTES>>>(                        // 8
        paths + (size_t)NN * NN, NN, bt2, DD, NN, buf0, buf1, nullptr);

    // ---- GCN 1 (same-level); CSR already built
    gemm_kernel<false><<<ggrid, 512, SMEM_BYTES>>>(buf1, DD, wt1, DD, DD,
                                                   nullptr, h, nullptr);
    gather_kernel<<<NN / 8, 256>>>(h, b_same, gout);

    // ---- GCN 2 (top-to-bottom)
    zero_cnt_kernel<<<NN / 256, 256>>>();
    hist_kernel<<<NE / 256, 256>>>(up_ei + NE);
    scan_kernel<<<1, 1024>>>();
    fill_kernel<<<NE / 256, 256>>>(up_ei, up_ei + NE);
    gemm_kernel<false><<<ggrid, 512, SMEM_BYTES>>>(gout, DD, wt2, DD, DD,
                                                   nullptr, h, nullptr);
    gather_kernel<<<NN / 8, 256>>>(h, b_top, out);
}

// round 14
// speedup vs baseline: 1.1211x; 1.1211x over previous
#include <cuda_runtime.h>
#include <mma.h>
#include <cstdint>

using namespace nvcuda;

#define NN 8192
#define DD 256
#define NE 131072

#define BM 64
#define BN 128
#define BK 32
#define LDAS 36
#define LDBS 132
#define LDCS 132
#define STAGE_FLOATS (BM * LDAS + BK * LDBS)   // 2304 + 4224 = 6528
#define NSTAGE 3
#define SMEM_BYTES (NSTAGE * STAGE_FLOATS * 4) // 78336

// scratch (device globals; no allocations allowed)
__device__ float g_buf0[NN * DD];
__device__ float g_buf1[NN * DD];
__device__ float g_h[NN * DD];
__device__ float g_gout[NN * DD];
__device__ float g_bt[NN * DD];        // tf32-RN pre-rounded B operand (level 0)
__device__ float g_bt2[NN * DD];       // pre-rounded output of level 0 (level-1 B)
__device__ float g_wt1[DD * DD];       // pre-rounded W_same
__device__ float g_wt2[DD * DD];       // pre-rounded W_top
__device__ int   g_cnt[NN];
__device__ int   g_rowstart[NN + 1];
__device__ int   g_cursor[NN];
__device__ int   g_csr_src[NE];
__device__ float g_dinv[NN];

__device__ __forceinline__ void cp_async16(void* smem_ptr, const void* gmem_ptr)
{
    uint32_t s = (uint32_t)__cvta_generic_to_shared(smem_ptr);
    asm volatile("cp.async.cg.shared.global [%0], [%1], 16;\n" :: "r"(s), "l"(gmem_ptr));
}
#define CP_COMMIT() asm volatile("cp.async.commit_group;\n" ::)

__device__ __forceinline__ float tf32_rna(float x)
{
    uint32_t u;
    asm("cvt.rna.tf32.f32 %0, %1;" : "=r"(u) : "f"(x));
    return __uint_as_float(u);
}

// ---------------------------------------------------------------------------
// Pre-round fp32 -> tf32(RN) bit pattern (low 13 bits zero). nElem4 float4s.
// ---------------------------------------------------------------------------
__global__ void round_tf32_kernel(const float* __restrict__ src, float* __restrict__ dst,
                                  int nElem4)
{
    int i = blockIdx.x * blockDim.x + threadIdx.x;
    if (i >= nElem4) return;
    float4 v = ((const float4*)src)[i];
    float4 o;
    o.x = tf32_rna(v.x);
    o.y = tf32_rna(v.y);
    o.z = tf32_rna(v.z);
    o.w = tf32_rna(v.w);
    ((float4*)dst)[i] = o;
}

// ---------------------------------------------------------------------------
// GEMM: C = A[M,K] @ B[K,256]; FUSE: Y = (resid + C) * 1/(rowsum(A)+1)
// CTA = 64x128 tile (grid.x = 2 halves of N=256), 128 threads = 4 warps,
// warp tile 64x32 (max fragment reuse). 3-stage cp.async pipeline.
// 256 CTAs -> 2 CTAs/SM -> 2 warps/SMSP hides LDS/barrier latency.
// A tile tf32-RN converted in place in smem (rowsum fused from pre-cvt bits);
// B must be pre-rounded to tf32 bits. Mainloop = pure LDS-frag + HMMA.
// If Yt != nullptr (FUSE only), also writes tf32-rounded copy of Y.
// ---------------------------------------------------------------------------
template <bool FUSE>
__global__ __launch_bounds__(128) void gemm_kernel(
    const float* __restrict__ A, int lda,
    const float* __restrict__ B, int ldb,
    int K,
    const float* __restrict__ resid,
    float* __restrict__ Y,
    float* __restrict__ Yt)
{
    extern __shared__ float pool[];
    __shared__ float invs[BM];

    const int tid = threadIdx.x;
    const int wn = tid >> 5;            // warp -> 32-col band of the 128 cols
    const int m0 = blockIdx.y * BM;
    const int n0 = blockIdx.x * BN;

    wmma::fragment<wmma::accumulator, 16, 16, 8, float> cf[4][2];
#pragma unroll
    for (int i = 0; i < 4; i++)
#pragma unroll
        for (int j = 0; j < 2; j++) wmma::fill_fragment(cf[i][j], 0.0f);

    float rs[4] = {0.f, 0.f, 0.f, 0.f};
    const int nIter = K / BK;

    // ---- prologue: stages 0 and 1
#pragma unroll
    for (int st = 0; st < 2; st++) {
        float* As = pool + st * STAGE_FLOATS;
        float* Bs = As + BM * LDAS;
        const int k0 = st * BK;
#pragma unroll
        for (int i = 0; i < 4; i++) {
            int e = tid + i * 128;           // 0..511
            int r = e >> 3, c4 = (e & 7) * 4;
            cp_async16(&As[r * LDAS + c4], &A[(size_t)(m0 + r) * lda + k0 + c4]);
        }
#pragma unroll
        for (int i = 0; i < 8; i++) {
            int e = tid + i * 128;           // 0..1023
            int r = e >> 5, c4 = (e & 31) * 4;
            cp_async16(&Bs[r * LDBS + c4], &B[(size_t)(k0 + r) * ldb + n0 + c4]);
        }
        CP_COMMIT();
    }

    for (int it = 0; it < nIter; ++it) {
        if (it == nIter - 1) asm volatile("cp.async.wait_group 0;\n" ::);
        else                 asm volatile("cp.async.wait_group 1;\n" ::);
        __syncthreads();

        // issue loads for stage it+2 (buffer reuse safe after barrier)
        const int tn = it + 2;
        if (tn < nIter) {
            float* Asn = pool + (tn % NSTAGE) * STAGE_FLOATS;
            float* Bsn = Asn + BM * LDAS;
            const int k0 = tn * BK;
#pragma unroll
            for (int i = 0; i < 4; i++) {
                int e = tid + i * 128;
                int r = e >> 3, c4 = (e & 7) * 4;
                cp_async16(&Asn[r * LDAS + c4], &A[(size_t)(m0 + r) * lda + k0 + c4]);
            }
#pragma unroll
            for (int i = 0; i < 8; i++) {
                int e = tid + i * 128;
                int r = e >> 5, c4 = (e & 31) * 4;
                cp_async16(&Bsn[r * LDBS + c4], &B[(size_t)(k0 + r) * ldb + n0 + c4]);
            }
            CP_COMMIT();
        }

        float* As = pool + (it % NSTAGE) * STAGE_FLOATS;
        float* Bs = As + BM * LDAS;

        // ---- in-place tf32-RN conversion of A tile (+ fused rowsum)
#pragma unroll
        for (int i = 0; i < 4; i++) {
            int e = tid + i * 128;
            int r = e >> 3, c4 = (e & 7) * 4;
            float4 v = *(const float4*)&As[r * LDAS + c4];
            if (FUSE) rs[i] += v.x + v.y + v.z + v.w;
            v.x = tf32_rna(v.x);
            v.y = tf32_rna(v.y);
            v.z = tf32_rna(v.z);
            v.w = tf32_rna(v.w);
            *(float4*)&As[r * LDAS + c4] = v;
        }
        __syncthreads();

        // ---- pure LDS + HMMA mainloop (no cvt)
#pragma unroll
        for (int kk = 0; kk < BK; kk += 8) {
            wmma::fragment<wmma::matrix_a, 16, 16, 8, wmma::precision::tf32, wmma::row_major> af[4];
            wmma::fragment<wmma::matrix_b, 16, 16, 8, wmma::precision::tf32, wmma::row_major> bf[2];
#pragma unroll
            for (int i = 0; i < 4; i++)
                wmma::load_matrix_sync(af[i], &As[(i * 16) * LDAS + kk], LDAS);
#pragma unroll
            for (int j = 0; j < 2; j++)
                wmma::load_matrix_sync(bf[j], &Bs[kk * LDBS + wn * 32 + j * 16], LDBS);
#pragma unroll
            for (int i = 0; i < 4; i++)
#pragma unroll
                for (int j = 0; j < 2; j++)
                    wmma::mma_sync(cf[i][j], af[i], bf[j], cf[i][j]);
        }
        // no end-of-iter barrier needed: next iter's top barrier suffices
    }

    if (FUSE) {
        // rows covered: r_i = (tid>>3) + 16*i ; reduce over 8 lanes sharing a row
#pragma unroll
        for (int i = 0; i < 4; i++) {
            float v = rs[i];
            v += __shfl_down_sync(0xffffffffu, v, 4, 8);
            v += __shfl_down_sync(0xffffffffu, v, 2, 8);
            v += __shfl_down_sync(0xffffffffu, v, 1, 8);
            if ((tid & 7) == 0) invs[(tid >> 3) + 16 * i] = 1.0f / (v + 1.0f);
        }
    }
    __syncthreads();

    float* Cs = pool;
#pragma unroll
    for (int i = 0; i < 4; i++)
#pragma unroll
        for (int j = 0; j < 2; j++)
            wmma::store_matrix_sync(&Cs[(i * 16) * LDCS + wn * 32 + j * 16],
                                    cf[i][j], LDCS, wmma::mem_row_major);
    __syncthreads();
#pragma unroll
    for (int i = 0; i < 16; i++) {
        int e = tid + i * 128;               // 0..2047
        int r = e >> 5, c4 = (e & 31) * 4;
        float4 c = *(float4*)&Cs[r * LDCS + c4];
        if (FUSE) {
            float4 x = *(const float4*)&resid[(size_t)(m0 + r) * DD + n0 + c4];
            float s = invs[r];
            c.x = (c.x + x.x) * s;
            c.y = (c.y + x.y) * s;
            c.z = (c.z + x.z) * s;
            c.w = (c.w + x.w) * s;
        }
        *(float4*)&Y[(size_t)(m0 + r) * DD + n0 + c4] = c;
        if (FUSE && Yt) {
            float4 t;
            t.x = tf32_rna(c.x);
            t.y = tf32_rna(c.y);
            t.z = tf32_rna(c.z);
            t.w = tf32_rna(c.w);
            *(float4*)&Yt[(size_t)(m0 + r) * DD + n0 + c4] = t;
        }
    }
}

// ---------------------------------------------------------------------------
// CSR build + gather GCN
// ---------------------------------------------------------------------------
__global__ void zero_cnt_kernel()
{
    int i = blockIdx.x * blockDim.x + threadIdx.x;
    if (i < NN) g_cnt[i] = 0;
}

__global__ void hist_kernel(const int* __restrict__ dst)
{
    int e = blockIdx.x * blockDim.x + threadIdx.x;
    if (e < NE) atomicAdd(&g_cnt[dst[e]], 1);
}

__global__ __launch_bounds__(1024) void scan_kernel()
{
    __shared__ int sh[1024];
    int t = threadIdx.x;
    int base = t * 8;
    int v[8];
    int s = 0;
#pragma unroll
    for (int i = 0; i < 8; i++) { v[i] = g_cnt[base + i]; s += v[i]; }
    sh[t] = s;
    __syncthreads();
    for (int off = 1; off < 1024; off <<= 1) {
        int x = (t >= off) ? sh[t - off] : 0;
        __syncthreads();
        sh[t] += x;
        __syncthreads();
    }
    int ex = sh[t] - s;
#pragma unroll
    for (int i = 0; i < 8; i++) {
        g_rowstart[base + i] = ex;
        g_cursor[base + i] = ex;
        g_dinv[base + i] = rsqrtf((float)v[i] + 1.0f);
        ex += v[i];
    }
    if (t == 1023) g_rowstart[NN] = ex;
}

__global__ void fill_kernel(const int* __restrict__ src, const int* __restrict__ dst)
{
    int e = blockIdx.x * blockDim.x + threadIdx.x;
    if (e >= NE) return;
    int p = atomicAdd(&g_cursor[dst[e]], 1);
    g_csr_src[p] = src[e];
}

__global__ __launch_bounds__(256) void gather_kernel(
    const float* __restrict__ h, const float* __restrict__ b, float* __restrict__ out)
{
    int wid = threadIdx.x >> 5;
    int lid = threadIdx.x & 31;
    int n = blockIdx.x * 8 + wid;
    if (n >= NN) return;
    int c0 = lid * 8;

    float dn = g_dinv[n];
    float4 b0 = *(const float4*)&b[c0];
    float4 b1 = *(const float4*)&b[c0 + 4];
    float4 h0 = *(const float4*)&h[(size_t)n * DD + c0];
    float4 h1 = *(const float4*)&h[(size_t)n * DD + c0 + 4];
    float sl = dn * dn;
    float4 a0, a1;
    a0.x = b0.x + sl * h0.x; a0.y = b0.y + sl * h0.y;
    a0.z = b0.z + sl * h0.z; a0.w = b0.w + sl * h0.w;
    a1.x = b1.x + sl * h1.x; a1.y = b1.y + sl * h1.y;
    a1.z = b1.z + sl * h1.z; a1.w = b1.w + sl * h1.w;

    int js = g_rowstart[n];
    int je = g_rowstart[n + 1];
    int j = js;
    for (; j + 1 < je; j += 2) {
        int s0 = g_csr_src[j];
        int s1 = g_csr_src[j + 1];
        float w0 = g_dinv[s0] * dn;
        float w1 = g_dinv[s1] * dn;
        float4 p0 = *(const float4*)&h[(size_t)s0 * DD + c0];
        float4 p1 = *(const float4*)&h[(size_t)s0 * DD + c0 + 4];
        float4 q0 = *(const float4*)&h[(size_t)s1 * DD + c0];
        float4 q1 = *(const float4*)&h[(size_t)s1 * DD + c0 + 4];
        a0.x += w0 * p0.x + w1 * q0.x; a0.y += w0 * p0.y + w1 * q0.y;
        a0.z += w0 * p0.z + w1 * q0.z; a0.w += w0 * p0.w + w1 * q0.w;
        a1.x += w0 * p1.x + w1 * q1.x; a1.y += w0 * p1.y + w1 * q1.y;
        a1.z += w0 * p1.z + w1 * q1.z; a1.w += w0 * p1.w + w1 * q1.w;
    }
    if (j < je) {
        int s0 = g_csr_src[j];
        float w0 = g_dinv[s0] * dn;
        float4 p0 = *(const float4*)&h[(size_t)s0 * DD + c0];
        float4 p1 = *(const float4*)&h[(size_t)s0 * DD + c0 + 4];
        a0.x += w0 * p0.x; a0.y += w0 * p0.y; a0.z += w0 * p0.z; a0.w += w0 * p0.w;
        a1.x += w0 * p1.x; a1.y += w0 * p1.y; a1.z += w0 * p1.z; a1.w += w0 * p1.w;
    }
    *(float4*)&out[(size_t)n * DD + c0] = a0;
    *(float4*)&out[(size_t)n * DD + c0 + 4] = a1;
}

extern "C" void kernel_launch(void* const* d_in, const int* in_sizes, int n_in,
                              void* d_out, int out_size)
{
    const float* emb    = (const float*)d_in[0];
    const float* paths  = (const float*)d_in[1];
    const int*   sm_ei  = (const int*)d_in[2];
    const int*   up_ei  = (const int*)d_in[3];
    const float* W_same = (const float*)d_in[4];
    const float* b_same = (const float*)d_in[5];
    const float* W_top  = (const float*)d_in[6];
    const float* b_top  = (const float*)d_in[7];
    float* out = (float*)d_out;

    float *buf0, *buf1, *h, *gout, *bt, *bt2, *wt1, *wt2;
    cudaGetSymbolAddress((void**)&buf0, g_buf0);
    cudaGetSymbolAddress((void**)&buf1, g_buf1);
    cudaGetSymbolAddress((void**)&h, g_h);
    cudaGetSymbolAddress((void**)&gout, g_gout);
    cudaGetSymbolAddress((void**)&bt, g_bt);
    cudaGetSymbolAddress((void**)&bt2, g_bt2);
    cudaGetSymbolAddress((void**)&wt1, g_wt1);
    cudaGetSymbolAddress((void**)&wt2, g_wt2);

    cudaFuncSetAttribute(gemm_kernel<true>,
                         cudaFuncAttributeMaxDynamicSharedMemorySize, SMEM_BYTES);
    cudaFuncSetAttribute(gemm_kernel<false>,
                         cudaFuncAttributeMaxDynamicSharedMemorySize, SMEM_BYTES);

    dim3 ggrid(DD / BN, NN / BM);   // (2, 128) = 256 CTAs -> 2 per SM
    int nr4 = NN * (DD / 4);
    int nw4 = DD * DD / 4;

    // Launch order keeps the level-0 big GEMM at index 3 (ncu profiles it).
    round_tf32_kernel<<<(nr4 + 255) / 256, 256>>>(emb, bt, nr4);         // 0
    round_tf32_kernel<<<(nw4 + 255) / 256, 256>>>(W_same, wt1, nw4);     // 1
    round_tf32_kernel<<<(nw4 + 255) / 256, 256>>>(W_top, wt2, nw4);      // 2
    gemm_kernel<true><<<ggrid, 128, SMEM_BYTES>>>(                        // 3 <- profiled
        paths, NN, bt, DD, NN, emb, buf0, bt2);
    zero_cnt_kernel<<<NN / 256, 256>>>();                                 // 4
    hist_kernel<<<NE / 256, 256>>>(sm_ei + NE);                           // 5
    scan_kernel<<<1, 1024>>>();                                           // 6
    fill_kernel<<<NE / 256, 256>>>(sm_ei, sm_ei + NE);                    // 7
    gemm_kernel<true><<<ggrid, 128, SMEM_BYTES>>>(                        // 8
        paths + (size_t)NN * NN, NN, bt2, DD, NN, buf0, buf1, nullptr);

    // ---- GCN 1 (same-level); CSR already built
    gemm_kernel<false><<<ggrid, 128, SMEM_BYTES>>>(buf1, DD, wt1, DD, DD,
                                                   nullptr, h, nullptr);
    gather_kernel<<<NN / 8, 256>>>(h, b_same, gout);

    // ---- GCN 2 (top-to-bottom)
    zero_cnt_kernel<<<NN / 256, 256>>>();
    hist_kernel<<<NE / 256, 256>>>(up_ei + NE);
    scan_kernel<<<1, 1024>>>();
    fill_kernel<<<NE / 256, 256>>>(up_ei, up_ei + NE);
    gemm_kernel<false><<<ggrid, 128, SMEM_BYTES>>>(gout, DD, wt2, DD, DD,
                                                   nullptr, h, nullptr);
    gather_kernel<<<NN / 8, 256>>>(h, b_top, out);
}